// round 3
// baseline (speedup 1.0000x reference)
#include <cuda_runtime.h>
#include <math.h>

#define NN  100000
#define EE_MAX 1200000
#define HID 64
#define IND 5

// ---------------- scratch (device globals; no allocations allowed) ----------
__device__ int   g_is64;
__device__ int   g_src[EE_MAX];
__device__ int   g_dst[EE_MAX];
__device__ int   g_cnt[NN];
__device__ int   g_off[NN];
__device__ int   g_fill[NN];
__device__ int   g_csr[EE_MAX];
__device__ float g_inv[NN];
__device__ int   g_bsum[128];
__device__ int   g_bsumex[128];
__device__ __align__(16) float g_ha[NN * HID];
__device__ __align__(16) float g_hb[NN * HID];
__device__ __align__(16) float g_stk1[2 * IND * HID];   // [U_top ; W@U_bot] L1
__device__ __align__(16) float g_stk2[2 * HID * HID];   // L2
__device__ __align__(16) float g_stk3[2 * HID * HID];   // L3
__device__ __align__(16) float g_cp1[HID], g_cp2[HID], g_cp3[HID];
__device__ float g_pst[1024], g_poc[1024];

// ------------- edge dtype detect + unpack (int32 vs int64 layout) -----------
__global__ void k_detect(const unsigned* __restrict__ ei) {
    // int64 nonneg values => every odd 32-bit word of the first 32 qwords is 0
    unsigned acc = 0u;
    for (int i = 1; i < 64; i += 2) acc |= ei[i];
    g_is64 = (acc == 0u) ? 1 : 0;
}

__global__ void k_convert(const int* __restrict__ ei, int E) {
    int is64 = g_is64;
    for (int i = blockIdx.x * blockDim.x + threadIdx.x; i < E;
         i += gridDim.x * blockDim.x) {
        int s, d;
        if (is64) {                // qwords: src[0..E) then dst[0..E)
            s = ei[2 * i];
            d = ei[2 * E + 2 * i];
        } else {                   // dwords: src[0..E) then dst[0..E)
            s = ei[i];
            d = ei[E + i];
        }
        g_src[i] = s;
        g_dst[i] = d;
    }
}

// ---------------- preprocessing: CSR build ----------------------------------
__global__ void k_zero() {
    int i = blockIdx.x * 256 + threadIdx.x;
    if (i < NN) { g_cnt[i] = 0; g_fill[i] = 0; }
}

__global__ void k_hist(int E) {
    for (int i = blockIdx.x * blockDim.x + threadIdx.x; i < E;
         i += gridDim.x * blockDim.x) {
        atomicAdd(&g_cnt[g_dst[i]], 1);
    }
}

__global__ void k_scan1() {
    __shared__ int sh[1024];
    int t = threadIdx.x;
    int i = blockIdx.x * 1024 + t;
    int v = (i < NN) ? g_cnt[i] : 0;
    sh[t] = v;
    __syncthreads();
    for (int o = 1; o < 1024; o <<= 1) {
        int a = (t >= o) ? sh[t - o] : 0;
        __syncthreads();
        sh[t] += a;
        __syncthreads();
    }
    if (i < NN) {
        g_off[i] = sh[t] - v;                 // exclusive prefix within block
        g_inv[i] = 1.0f / (float)(v + 1);     // +1 for self loop
    }
    if (t == 1023) g_bsum[blockIdx.x] = sh[t];
}

__global__ void k_scan2(int nb) {
    __shared__ int sh[128];
    int t = threadIdx.x;
    int v = (t < nb) ? g_bsum[t] : 0;
    sh[t] = v;
    __syncthreads();
    for (int o = 1; o < 128; o <<= 1) {
        int a = (t >= o) ? sh[t - o] : 0;
        __syncthreads();
        sh[t] += a;
        __syncthreads();
    }
    g_bsumex[t] = sh[t] - v;
}

__global__ void k_scan3() {
    int i = blockIdx.x * 256 + threadIdx.x;
    if (i < NN) g_off[i] += g_bsumex[i >> 10];
}

__global__ void k_fill(int E) {
    for (int i = blockIdx.x * blockDim.x + threadIdx.x; i < E;
         i += gridDim.x * blockDim.x) {
        int d = g_dst[i];
        int p = g_off[d] + atomicAdd(&g_fill[d], 1);
        g_csr[p] = g_src[i];
    }
}

// ------ weight folding: stk = [U_top ; W @ U_bot], cp = b @ U_bot + c -------
__global__ void k_fold(const float* __restrict__ W, const float* __restrict__ b,
                       const float* __restrict__ U, const float* __restrict__ c,
                       int D, int layer) {
    float* stk = (layer == 1) ? g_stk1 : (layer == 2) ? g_stk2 : g_stk3;
    float* cp  = (layer == 1) ? g_cp1  : (layer == 2) ? g_cp2  : g_cp3;
    int idx = blockIdx.x * blockDim.x + threadIdx.x;
    if (idx >= (2 * D + 1) * 64) return;
    int k = idx >> 6, o = idx & 63;
    const float* Ub = U + D * 64;             // bottom half of U: rows D..2D-1
    if (k < D) {
        stk[k * 64 + o] = U[k * 64 + o];      // top half passthrough
    } else if (k < 2 * D) {
        float s = 0.0f;
        for (int m = 0; m < 64; ++m) s += W[(k - D) * 64 + m] * Ub[m * 64 + o];
        stk[k * 64 + o] = s;
    } else {
        float s = c[o];
        for (int m = 0; m < 64; ++m) s += b[m] * Ub[m * 64 + o];
        cp[o] = s;
    }
}

// ------- fused layer: gather-mean + GEMM([x||s] @ stk) + bias + relu --------
template <int D>
__global__ void __launch_bounds__(256)
k_layer(const float* __restrict__ x0, float* __restrict__ out3, int layer) {
    constexpr int K    = 2 * D;
    constexpr int TM   = 64;
    constexpr int XSTR = TM + 2;              // 66: conflict-free, 8B rows
    __shared__ __align__(16) float XS[K][XSTR];  // rows 0..D-1 = x, D..2D-1 = mean

    const float* xin = (layer == 1) ? x0 : (layer == 2 ? g_ha : g_hb);
    float*       out = (layer == 1) ? g_ha : (layer == 2 ? g_hb : out3);
    const float* stk = (layer == 1) ? g_stk1 : (layer == 2 ? g_stk2 : g_stk3);
    const float* cp  = (layer == 1) ? g_cp1  : (layer == 2 ? g_cp2  : g_cp3);

    const int t = threadIdx.x;
    const int node0 = blockIdx.x * TM;

    // x tile, transposed (k-major)
    for (int idx = t; idx < TM * D; idx += 256) {
        int n = idx / D, k = idx - n * D;
        int node = node0 + n;
        XS[k][n] = (node < NN) ? xin[node * D + k] : 0.0f;
    }

    // gather: warp per node, mean over incoming edges + self loop
    const int warp = t >> 5, lane = t & 31;
    constexpr int NC = (D + 31) / 32;
    for (int r = 0; r < TM / 8; ++r) {
        int n = r * 8 + warp;
        int node = node0 + n;
        if (node < NN) {
            float acc[NC];
#pragma unroll
            for (int cc = 0; cc < NC; ++cc) {
                int col = lane + 32 * cc;
                acc[cc] = (col < D) ? xin[node * D + col] : 0.0f;  // self loop
            }
            int e0  = g_off[node];
            int deg = g_cnt[node];
            int s = (deg > 0) ? g_csr[e0] : 0;
            for (int e = 0; e < deg; ++e) {
                int sn = (e + 1 < deg) ? g_csr[e0 + e + 1] : 0;    // prefetch
#pragma unroll
                for (int cc = 0; cc < NC; ++cc) {
                    int col = lane + 32 * cc;
                    if (col < D) acc[cc] += xin[s * D + col];
                }
                s = sn;
            }
            float iv = g_inv[node];
#pragma unroll
            for (int cc = 0; cc < NC; ++cc) {
                int col = lane + 32 * cc;
                if (col < D) XS[D + col][n] = acc[cc] * iv;
            }
        } else {
#pragma unroll
            for (int cc = 0; cc < NC; ++cc) {
                int col = lane + 32 * cc;
                if (col < D) XS[D + col][n] = 0.0f;
            }
        }
    }
    __syncthreads();

    // GEMM: 256 threads as 16x16, each computes 4 nodes x 4 outputs
    const int tx = t & 15, ty = t >> 4;
    const int o4 = tx * 4, n4 = ty * 4;
    float acc[4][4];
#pragma unroll
    for (int i = 0; i < 4; ++i)
#pragma unroll
        for (int j = 0; j < 4; ++j) acc[i][j] = 0.0f;

#pragma unroll 4
    for (int k = 0; k < K; ++k) {
        float4 w  = __ldg((const float4*)&stk[k * 64 + o4]);
        float2 xa = *(const float2*)&XS[k][n4];
        float2 xb = *(const float2*)&XS[k][n4 + 2];
        float xv[4] = {xa.x, xa.y, xb.x, xb.y};
#pragma unroll
        for (int i = 0; i < 4; ++i) {
            acc[i][0] += xv[i] * w.x;
            acc[i][1] += xv[i] * w.y;
            acc[i][2] += xv[i] * w.z;
            acc[i][3] += xv[i] * w.w;
        }
    }

    float cb0 = __ldg(&cp[o4]),     cb1 = __ldg(&cp[o4 + 1]);
    float cb2 = __ldg(&cp[o4 + 2]), cb3 = __ldg(&cp[o4 + 3]);
#pragma unroll
    for (int i = 0; i < 4; ++i) {
        int node = node0 + n4 + i;
        if (node < NN) {
            float v0 = fmaxf(acc[i][0] + cb0, 0.0f);
            float v1 = fmaxf(acc[i][1] + cb1, 0.0f);
            float v2 = fmaxf(acc[i][2] + cb2, 0.0f);
            float v3 = fmaxf(acc[i][3] + cb3, 0.0f);
            float2* p = (float2*)&out[node * 64 + o4];   // 8B-aligned
            p[0] = make_float2(v0, v1);
            p[1] = make_float2(v2, v3);
        }
    }
}

// ---------------- heads: state[N,2], sigmoid-mean, mean ---------------------
__global__ void __launch_bounds__(256)
k_heads(const float* __restrict__ h, const float* __restrict__ Ws,
        const float* __restrict__ bs, const float* __restrict__ Wst,
        const float* __restrict__ bst, const float* __restrict__ Wo,
        const float* __restrict__ bo, float* __restrict__ out_state) {
    __shared__ float wst[8], woc[8];
    int t = threadIdx.x, warp = t >> 5, lane = t & 31;
    int gw = blockIdx.x * 8 + warp;

    float ws0a = Ws[lane * 2 + 0], ws0b = Ws[(lane + 32) * 2 + 0];
    float ws1a = Ws[lane * 2 + 1], ws1b = Ws[(lane + 32) * 2 + 1];
    float wsta = Wst[lane], wstb = Wst[lane + 32];
    float woa  = Wo[lane],  wob  = Wo[lane + 32];
    float bs0 = bs[0], bs1 = bs[1], bstv = bst[0], bov = bo[0];

    float sum_st = 0.0f, sum_oc = 0.0f;
    for (int node = gw; node < NN; node += 8192) {
        float h0 = h[node * 64 + lane];
        float h1 = h[node * 64 + lane + 32];
        float d0 = h0 * ws0a + h1 * ws0b;
        float d1 = h0 * ws1a + h1 * ws1b;
        float d2 = h0 * wsta + h1 * wstb;
        float d3 = h0 * woa  + h1 * wob;
#pragma unroll
        for (int o = 16; o > 0; o >>= 1) {
            d0 += __shfl_xor_sync(0xffffffffu, d0, o);
            d1 += __shfl_xor_sync(0xffffffffu, d1, o);
            d2 += __shfl_xor_sync(0xffffffffu, d2, o);
            d3 += __shfl_xor_sync(0xffffffffu, d3, o);
        }
        if (lane == 0) {
            out_state[node * 2 + 0] = d0 + bs0;
            out_state[node * 2 + 1] = d1 + bs1;
            sum_st += 1.0f / (1.0f + expf(-(d2 + bstv)));
            sum_oc += d3 + bov;
        }
    }
    if (lane == 0) { wst[warp] = sum_st; woc[warp] = sum_oc; }
    __syncthreads();
    if (t == 0) {
        float a = 0.0f, b = 0.0f;
        for (int i = 0; i < 8; ++i) { a += wst[i]; b += woc[i]; }
        g_pst[blockIdx.x] = a;
        g_poc[blockIdx.x] = b;
    }
}

__global__ void k_final(float* __restrict__ out) {
    __shared__ float sa[1024], sb[1024];
    int t = threadIdx.x;
    sa[t] = g_pst[t];
    sb[t] = g_poc[t];
    __syncthreads();
    for (int o = 512; o > 0; o >>= 1) {
        if (t < o) { sa[t] += sa[t + o]; sb[t] += sb[t + o]; }
        __syncthreads();
    }
    if (t == 0) {
        out[200000] = sa[0] / (float)NN;
        out[200001] = sb[0] / (float)NN;
    }
}

// ---------------- launch -----------------------------------------------------
extern "C" void kernel_launch(void* const* d_in, const int* in_sizes, int n_in,
                              void* d_out, int out_size) {
    const float* x   = (const float*)d_in[0];
    const void*  ei  = d_in[1];
    const float* W1 = (const float*)d_in[2],  *b1 = (const float*)d_in[3];
    const float* U1 = (const float*)d_in[4],  *c1 = (const float*)d_in[5];
    const float* W2 = (const float*)d_in[6],  *b2 = (const float*)d_in[7];
    const float* U2 = (const float*)d_in[8],  *c2 = (const float*)d_in[9];
    const float* W3 = (const float*)d_in[10], *b3 = (const float*)d_in[11];
    const float* U3 = (const float*)d_in[12], *c3 = (const float*)d_in[13];
    const float* Ws = (const float*)d_in[14], *bs = (const float*)d_in[15];
    const float* Wst = (const float*)d_in[16], *bst = (const float*)d_in[17];
    const float* Wo = (const float*)d_in[18],  *bo = (const float*)d_in[19];
    float* out = (float*)d_out;

    int E = in_sizes[1] / 2;      // element count / 2 (same for i32 and i64)

    // edge decode (dtype-agnostic) + CSR build
    k_detect<<<1, 1>>>((const unsigned*)ei);
    k_convert<<<2048, 256>>>((const int*)ei, E);
    k_zero<<<(NN + 255) / 256, 256>>>();
    k_hist<<<2048, 256>>>(E);
    k_scan1<<<(NN + 1023) / 1024, 1024>>>();
    k_scan2<<<1, 128>>>((NN + 1023) / 1024);
    k_scan3<<<(NN + 255) / 256, 256>>>();
    k_fill<<<2048, 256>>>(E);

    // weight folding
    k_fold<<<((2 * IND + 1) * 64 + 255) / 256, 256>>>(W1, b1, U1, c1, IND, 1);
    k_fold<<<((2 * HID + 1) * 64 + 255) / 256, 256>>>(W2, b2, U2, c2, HID, 2);
    k_fold<<<((2 * HID + 1) * 64 + 255) / 256, 256>>>(W3, b3, U3, c3, HID, 3);

    // layers (static shared memory only)
    int grid = (NN + 63) / 64;
    k_layer<IND><<<grid, 256>>>(x, nullptr, 1);
    k_layer<HID><<<grid, 256>>>(nullptr, nullptr, 2);
    k_layer<HID><<<grid, 256>>>(nullptr, out + 200002, 3);

    // heads + scalar means
    k_heads<<<1024, 256>>>(out + 200002, Ws, bs, Wst, bst, Wo, bo, out);
    k_final<<<1, 1024>>>(out);
}

// round 5
// speedup vs baseline: 1.0120x; 1.0120x over previous
#include <cuda_runtime.h>
#include <math.h>

#define NN  100000
#define EE_MAX 1200000
#define HID 64
#define IND 5

typedef unsigned long long u64;

// ---------------- scratch (device globals; no allocations allowed) ----------
__device__ int   g_is64;
__device__ int   g_cnt[NN];
__device__ int   g_off[NN];
__device__ int   g_fill[NN];
__device__ int   g_csr[EE_MAX];
__device__ float g_inv[NN];
__device__ int   g_bsum[128];
__device__ int   g_bsumex[128];
__device__ __align__(16) float g_ha[NN * HID];
__device__ __align__(16) float g_hb[NN * HID];
__device__ __align__(16) float g_stk1[2 * IND * HID];   // [U_top ; W@U_bot] L1
__device__ __align__(16) float g_stk2[2 * HID * HID];   // L2
__device__ __align__(16) float g_stk3[2 * HID * HID];   // L3
__device__ __align__(16) float g_cp1[HID], g_cp2[HID], g_cp3[HID];
__device__ float g_pst[1024], g_poc[1024];

// ---------------- packed f32x2 helpers (FFMA2 path) -------------------------
__device__ __forceinline__ u64 pack2(float lo, float hi) {
    u64 r;
    asm("mov.b64 %0, {%1, %2};" : "=l"(r) : "f"(lo), "f"(hi));
    return r;
}
__device__ __forceinline__ u64 ffma2(u64 a, u64 b, u64 c) {
    u64 d;
    asm("fma.rn.f32x2 %0, %1, %2, %3;" : "=l"(d) : "l"(a), "l"(b), "l"(c));
    return d;
}
__device__ __forceinline__ void unpack2(u64 v, float& lo, float& hi) {
    asm("mov.b64 {%0, %1}, %2;" : "=f"(lo), "=f"(hi) : "l"(v));
}

// ------------- edge dtype detect (int32 vs int64 storage) -------------------
__global__ void k_detect(const unsigned* __restrict__ ei) {
    // int64 nonneg values => every odd 32-bit word of the first 32 qwords is 0
    unsigned acc = 0u;
    for (int i = 1; i < 64; i += 2) acc |= ei[i];
    g_is64 = (acc == 0u) ? 1 : 0;
}

// ---------------- preprocessing: CSR build ----------------------------------
__global__ void k_zero() {
    int i = blockIdx.x * 256 + threadIdx.x;
    if (i < NN) { g_cnt[i] = 0; g_fill[i] = 0; }
}

__global__ void k_hist(const int* __restrict__ ei, int E) {
    int is64 = g_is64;
    for (int i = blockIdx.x * blockDim.x + threadIdx.x; i < E;
         i += gridDim.x * blockDim.x) {
        int d = is64 ? ei[2 * (E + i)] : ei[E + i];
        atomicAdd(&g_cnt[d], 1);
    }
}

__global__ void k_scan1() {
    __shared__ int sh[1024];
    int t = threadIdx.x;
    int i = blockIdx.x * 1024 + t;
    int v = (i < NN) ? g_cnt[i] : 0;
    sh[t] = v;
    __syncthreads();
    for (int o = 1; o < 1024; o <<= 1) {
        int a = (t >= o) ? sh[t - o] : 0;
        __syncthreads();
        sh[t] += a;
        __syncthreads();
    }
    if (i < NN) {
        g_off[i] = sh[t] - v;                 // exclusive prefix within block
        g_inv[i] = 1.0f / (float)(v + 1);     // +1 for self loop
    }
    if (t == 1023) g_bsum[blockIdx.x] = sh[t];
}

__global__ void k_scan2(int nb) {
    __shared__ int sh[128];
    int t = threadIdx.x;
    int v = (t < nb) ? g_bsum[t] : 0;
    sh[t] = v;
    __syncthreads();
    for (int o = 1; o < 128; o <<= 1) {
        int a = (t >= o) ? sh[t - o] : 0;
        __syncthreads();
        sh[t] += a;
        __syncthreads();
    }
    g_bsumex[t] = sh[t] - v;
}

__global__ void k_scan3() {
    int i = blockIdx.x * 256 + threadIdx.x;
    if (i < NN) g_off[i] += g_bsumex[i >> 10];
}

__global__ void k_fill(const int* __restrict__ ei, int E) {
    int is64 = g_is64;
    for (int i = blockIdx.x * blockDim.x + threadIdx.x; i < E;
         i += gridDim.x * blockDim.x) {
        int s, d;
        if (is64) { s = ei[2 * i]; d = ei[2 * (E + i)]; }
        else      { s = ei[i];     d = ei[E + i]; }
        int p = g_off[d] + atomicAdd(&g_fill[d], 1);
        g_csr[p] = s;
    }
}

// ------ weight folding: stk = [U_top ; W @ U_bot], cp = b @ U_bot + c -------
__device__ __forceinline__ void fold_one(const float* W, const float* b,
                                         const float* U, const float* c,
                                         int D, float* stk, float* cp, int idx) {
    int k = idx >> 6, o = idx & 63;
    const float* Ub = U + D * 64;             // bottom half of U: rows D..2D-1
    if (k < D) {
        stk[k * 64 + o] = U[k * 64 + o];      // top half passthrough
    } else if (k < 2 * D) {
        float s = 0.0f;
        for (int m = 0; m < 64; ++m) s += W[(k - D) * 64 + m] * Ub[m * 64 + o];
        stk[k * 64 + o] = s;
    } else {
        float s = c[o];
        for (int m = 0; m < 64; ++m) s += b[m] * Ub[m * 64 + o];
        cp[o] = s;
    }
}

__global__ void k_fold_all(const float* W1, const float* b1, const float* U1, const float* c1,
                           const float* W2, const float* b2, const float* U2, const float* c2,
                           const float* W3, const float* b3, const float* U3, const float* c3) {
    const int n1 = (2 * IND + 1) * 64;        // 704
    const int n2 = (2 * HID + 1) * 64;        // 8256
    int idx = blockIdx.x * 256 + threadIdx.x;
    if (idx < n1)                fold_one(W1, b1, U1, c1, IND, g_stk1, g_cp1, idx);
    else if (idx < n1 + n2)      fold_one(W2, b2, U2, c2, HID, g_stk2, g_cp2, idx - n1);
    else if (idx < n1 + 2 * n2)  fold_one(W3, b3, U3, c3, HID, g_stk3, g_cp3, idx - n1 - n2);
}

// ------- fused layer: gather-mean + GEMM([x||s] @ stk) + bias + relu --------
template <int D>
__global__ void __launch_bounds__(256)
k_layer(const float* __restrict__ x0, float* __restrict__ out3, int layer) {
    constexpr int K    = 2 * D;
    constexpr int TM   = 64;
    constexpr int XSTR = TM + 2;              // 66: conflict-free, 8B rows
    __shared__ __align__(16) float XS[K][XSTR];  // rows 0..D-1 = x, D..2D-1 = mean

    const float* xin = (layer == 1) ? x0 : (layer == 2 ? g_ha : g_hb);
    float*       out = (layer == 1) ? g_ha : (layer == 2 ? g_hb : out3);
    const float* stk = (layer == 1) ? g_stk1 : (layer == 2 ? g_stk2 : g_stk3);
    const float* cp  = (layer == 1) ? g_cp1  : (layer == 2 ? g_cp2  : g_cp3);

    const int t = threadIdx.x;
    const int node0 = blockIdx.x * TM;

    // x tile, transposed (k-major)
    for (int idx = t; idx < TM * D; idx += 256) {
        int n = idx / D, k = idx - n * D;
        int node = node0 + n;
        XS[k][n] = (node < NN) ? xin[node * D + k] : 0.0f;
    }

    // gather: warp per node, mean over incoming edges + self loop.
    // 4-edge unroll with index prefetch => 4*NC independent loads in flight.
    const int warp = t >> 5, lane = t & 31;
    constexpr int NC = (D + 31) / 32;
    for (int r = 0; r < TM / 8; ++r) {
        int n = r * 8 + warp;
        int node = node0 + n;
        if (node >= NN) {
#pragma unroll
            for (int cc = 0; cc < NC; ++cc) {
                int col = lane + 32 * cc;
                if (col < D) XS[D + col][n] = 0.0f;
            }
            continue;
        }
        float a0[NC], a1[NC], a2[NC], a3[NC];
#pragma unroll
        for (int cc = 0; cc < NC; ++cc) {
            int col = lane + 32 * cc;
            a0[cc] = (col < D) ? xin[node * D + col] : 0.0f;   // self loop
            a1[cc] = 0.0f; a2[cc] = 0.0f; a3[cc] = 0.0f;
        }
        const int e0  = g_off[node];
        const int deg = g_cnt[node];
        const int last = e0 + deg - 1;
        int e = 0;
        if (deg >= 4) {
            int s0 = g_csr[e0], s1 = g_csr[e0 + 1];
            int s2 = g_csr[e0 + 2], s3 = g_csr[e0 + 3];
            while (e + 4 <= deg) {
                int p = e0 + e + 4;
                int t0 = g_csr[min(p,     last)];
                int t1 = g_csr[min(p + 1, last)];
                int t2 = g_csr[min(p + 2, last)];
                int t3 = g_csr[min(p + 3, last)];
                const float* q0 = xin + (size_t)s0 * D;
                const float* q1 = xin + (size_t)s1 * D;
                const float* q2 = xin + (size_t)s2 * D;
                const float* q3 = xin + (size_t)s3 * D;
#pragma unroll
                for (int cc = 0; cc < NC; ++cc) {
                    int col = lane + 32 * cc;
                    if (col < D) {
                        a0[cc] += q0[col];
                        a1[cc] += q1[col];
                        a2[cc] += q2[col];
                        a3[cc] += q3[col];
                    }
                }
                s0 = t0; s1 = t1; s2 = t2; s3 = t3;
                e += 4;
            }
        }
        for (; e < deg; ++e) {
            int s = g_csr[e0 + e];
            const float* q = xin + (size_t)s * D;
#pragma unroll
            for (int cc = 0; cc < NC; ++cc) {
                int col = lane + 32 * cc;
                if (col < D) a0[cc] += q[col];
            }
        }
        float iv = g_inv[node];
#pragma unroll
        for (int cc = 0; cc < NC; ++cc) {
            int col = lane + 32 * cc;
            if (col < D) XS[D + col][n] = ((a0[cc] + a1[cc]) + (a2[cc] + a3[cc])) * iv;
        }
    }
    __syncthreads();

    // GEMM: 256 threads as 16x16, each 4 nodes x 4 outputs, packed f32x2
    // over node pairs (FFMA2: 2 FMA per inst on the fma pipe).
    const int tx = t & 15, ty = t >> 4;
    const int o4 = tx * 4, n4 = ty * 4;
    u64 accA[4], accB[4];                     // accA[o] = {n4, n4+1}, accB = {n4+2, n4+3}
#pragma unroll
    for (int o = 0; o < 4; ++o) { accA[o] = 0ull; accB[o] = 0ull; }

#pragma unroll 4
    for (int k = 0; k < K; ++k) {
        float4 w = __ldg((const float4*)&stk[k * 64 + o4]);
        u64 w0 = pack2(w.x, w.x), w1 = pack2(w.y, w.y);
        u64 w2 = pack2(w.z, w.z), w3 = pack2(w.w, w.w);
        u64 xA = *(const u64*)&XS[k][n4];
        u64 xB = *(const u64*)&XS[k][n4 + 2];
        accA[0] = ffma2(xA, w0, accA[0]);
        accA[1] = ffma2(xA, w1, accA[1]);
        accA[2] = ffma2(xA, w2, accA[2]);
        accA[3] = ffma2(xA, w3, accA[3]);
        accB[0] = ffma2(xB, w0, accB[0]);
        accB[1] = ffma2(xB, w1, accB[1]);
        accB[2] = ffma2(xB, w2, accB[2]);
        accB[3] = ffma2(xB, w3, accB[3]);
    }

    float cb[4];
    cb[0] = __ldg(&cp[o4]);     cb[1] = __ldg(&cp[o4 + 1]);
    cb[2] = __ldg(&cp[o4 + 2]); cb[3] = __ldg(&cp[o4 + 3]);

    float r0[4], r1[4], r2[4], r3[4];         // per node: 4 outputs
#pragma unroll
    for (int o = 0; o < 4; ++o) {
        float lo, hi;
        unpack2(accA[o], lo, hi);
        r0[o] = fmaxf(lo + cb[o], 0.0f);
        r1[o] = fmaxf(hi + cb[o], 0.0f);
        unpack2(accB[o], lo, hi);
        r2[o] = fmaxf(lo + cb[o], 0.0f);
        r3[o] = fmaxf(hi + cb[o], 0.0f);
    }
    // NOTE: out for layer 3 is d_out+200002 floats => base only 8B-aligned.
    // Use float2 (8B) stores, never float4, on the output path.
#pragma unroll
    for (int i = 0; i < 4; ++i) {
        int node = node0 + n4 + i;
        if (node < NN) {
            const float* rr = (i == 0) ? r0 : (i == 1) ? r1 : (i == 2) ? r2 : r3;
            float2* p = (float2*)&out[node * 64 + o4];
            p[0] = make_float2(rr[0], rr[1]);
            p[1] = make_float2(rr[2], rr[3]);
        }
    }
}

// ---------------- heads: state[N,2], sigmoid-mean, mean ---------------------
__global__ void __launch_bounds__(256)
k_heads(const float* __restrict__ h, const float* __restrict__ Ws,
        const float* __restrict__ bs, const float* __restrict__ Wst,
        const float* __restrict__ bst, const float* __restrict__ Wo,
        const float* __restrict__ bo, float* __restrict__ out_state) {
    __shared__ float wst[8], woc[8];
    int t = threadIdx.x, warp = t >> 5, lane = t & 31;
    int gw = blockIdx.x * 8 + warp;

    float ws0a = Ws[lane * 2 + 0], ws0b = Ws[(lane + 32) * 2 + 0];
    float ws1a = Ws[lane * 2 + 1], ws1b = Ws[(lane + 32) * 2 + 1];
    float wsta = Wst[lane], wstb = Wst[lane + 32];
    float woa  = Wo[lane],  wob  = Wo[lane + 32];
    float bs0 = bs[0], bs1 = bs[1], bstv = bst[0], bov = bo[0];

    float sum_st = 0.0f, sum_oc = 0.0f;
    for (int node = gw; node < NN; node += 8192) {
        float h0 = h[node * 64 + lane];
        float h1 = h[node * 64 + lane + 32];
        float d0 = h0 * ws0a + h1 * ws0b;
        float d1 = h0 * ws1a + h1 * ws1b;
        float d2 = h0 * wsta + h1 * wstb;
        float d3 = h0 * woa  + h1 * wob;
#pragma unroll
        for (int o = 16; o > 0; o >>= 1) {
            d0 += __shfl_xor_sync(0xffffffffu, d0, o);
            d1 += __shfl_xor_sync(0xffffffffu, d1, o);
            d2 += __shfl_xor_sync(0xffffffffu, d2, o);
            d3 += __shfl_xor_sync(0xffffffffu, d3, o);
        }
        if (lane == 0) {
            out_state[node * 2 + 0] = d0 + bs0;
            out_state[node * 2 + 1] = d1 + bs1;
            sum_st += 1.0f / (1.0f + expf(-(d2 + bstv)));
            sum_oc += d3 + bov;
        }
    }
    if (lane == 0) { wst[warp] = sum_st; woc[warp] = sum_oc; }
    __syncthreads();
    if (t == 0) {
        float a = 0.0f, b = 0.0f;
        for (int i = 0; i < 8; ++i) { a += wst[i]; b += woc[i]; }
        g_pst[blockIdx.x] = a;
        g_poc[blockIdx.x] = b;
    }
}

__global__ void k_final(float* __restrict__ out) {
    __shared__ float sa[1024], sb[1024];
    int t = threadIdx.x;
    sa[t] = g_pst[t];
    sb[t] = g_poc[t];
    __syncthreads();
    for (int o = 512; o > 0; o >>= 1) {
        if (t < o) { sa[t] += sa[t + o]; sb[t] += sb[t + o]; }
        __syncthreads();
    }
    if (t == 0) {
        out[200000] = sa[0] / (float)NN;
        out[200001] = sb[0] / (float)NN;
    }
}

// ---------------- launch -----------------------------------------------------
extern "C" void kernel_launch(void* const* d_in, const int* in_sizes, int n_in,
                              void* d_out, int out_size) {
    const float* x   = (const float*)d_in[0];
    const int*   ei  = (const int*)d_in[1];
    const float* W1 = (const float*)d_in[2],  *b1 = (const float*)d_in[3];
    const float* U1 = (const float*)d_in[4],  *c1 = (const float*)d_in[5];
    const float* W2 = (const float*)d_in[6],  *b2 = (const float*)d_in[7];
    const float* U2 = (const float*)d_in[8],  *c2 = (const float*)d_in[9];
    const float* W3 = (const float*)d_in[10], *b3 = (const float*)d_in[11];
    const float* U3 = (const float*)d_in[12], *c3 = (const float*)d_in[13];
    const float* Ws = (const float*)d_in[14], *bs = (const float*)d_in[15];
    const float* Wst = (const float*)d_in[16], *bst = (const float*)d_in[17];
    const float* Wo = (const float*)d_in[18],  *bo = (const float*)d_in[19];
    float* out = (float*)d_out;

    int E = in_sizes[1] / 2;      // element count / 2 (same for i32 and i64)

    // edge decode (dtype-agnostic) + CSR build
    k_detect<<<1, 1>>>((const unsigned*)ei);
    k_zero<<<(NN + 255) / 256, 256>>>();
    k_hist<<<2048, 256>>>(ei, E);
    k_scan1<<<(NN + 1023) / 1024, 1024>>>();
    k_scan2<<<1, 128>>>((NN + 1023) / 1024);
    k_scan3<<<(NN + 255) / 256, 256>>>();
    k_fill<<<2048, 256>>>(ei, E);

    // weight folding (single launch)
    int fold_elems = (2 * IND + 1) * 64 + 2 * (2 * HID + 1) * 64;
    k_fold_all<<<(fold_elems + 255) / 256, 256>>>(W1, b1, U1, c1,
                                                  W2, b2, U2, c2,
                                                  W3, b3, U3, c3);

    // layers (static shared memory only)
    int grid = (NN + 63) / 64;
    k_layer<IND><<<grid, 256>>>(x, nullptr, 1);
    k_layer<HID><<<grid, 256>>>(nullptr, nullptr, 2);
    k_layer<HID><<<grid, 256>>>(nullptr, out + 200002, 3);

    // heads + scalar means
    k_heads<<<1024, 256>>>(out + 200002, Ws, bs, Wst, bst, Wo, bo, out);
    k_final<<<1, 1024>>>(out);
}

// round 8
// speedup vs baseline: 1.0979x; 1.0849x over previous
#include <cuda_runtime.h>
#include <math.h>

#define NN  100000
#define EE_MAX 1200000
#define HID 64
#define IND 5

typedef unsigned long long u64;

// ---------------- scratch (device globals; no allocations allowed) ----------
__device__ int      g_cnt[NN];
__device__ int      g_off[NN];
__device__ int      g_fill[NN];
__device__ int      g_csr[EE_MAX];
__device__ float    g_inv[NN];
__device__ int      g_total;
__device__ unsigned g_done;
__device__ __align__(16) float g_ha[NN * HID];
__device__ __align__(16) float g_hb[NN * HID];
__device__ __align__(16) float g_stk1[2 * IND * HID];   // [U_top ; W@U_bot] L1
__device__ __align__(16) float g_stk2[2 * HID * HID];   // L2
__device__ __align__(16) float g_stk3[2 * HID * HID];   // L3
__device__ __align__(16) float g_cp1[HID], g_cp2[HID], g_cp3[HID];
__device__ float g_pst[1024], g_poc[1024];

// ---------------- packed f32x2 helpers (FFMA2 path) -------------------------
__device__ __forceinline__ u64 pack2(float lo, float hi) {
    u64 r;
    asm("mov.b64 %0, {%1, %2};" : "=l"(r) : "f"(lo), "f"(hi));
    return r;
}
__device__ __forceinline__ u64 ffma2(u64 a, u64 b, u64 c) {
    u64 d;
    asm("fma.rn.f32x2 %0, %1, %2, %3;" : "=l"(d) : "l"(a), "l"(b), "l"(c));
    return d;
}
__device__ __forceinline__ void unpack2(u64 v, float& lo, float& hi) {
    asm("mov.b64 {%0, %1}, %2;" : "=f"(lo), "=f"(hi) : "l"(v));
}

// ---- inline int64-vs-int32 edge dtype detect (cheap, per-block) ------------
__device__ __forceinline__ int detect64(const int* ei) {
    const unsigned* u = (const unsigned*)ei;
    unsigned acc = 0u;
#pragma unroll
    for (int i = 1; i < 64; i += 2) acc |= u[i];   // odd words all 0 => int64
    return acc == 0u;
}

// ---------------- launch 0: zero counters -----------------------------------
__global__ void k_zero() {
    int i = blockIdx.x * 256 + threadIdx.x;
    if (i < NN) { g_cnt[i] = 0; g_fill[i] = 0; }
    if (i == 0) { g_total = 0; g_done = 0u; }
}

// ---------------- launch 1: histogram of dst --------------------------------
__global__ void k_hist(const int* __restrict__ ei, int E) {
    int is64 = detect64(ei);
    for (int i = blockIdx.x * blockDim.x + threadIdx.x; i < E;
         i += gridDim.x * blockDim.x) {
        int d = is64 ? ei[2 * (E + i)] : ei[E + i];
        atomicAdd(&g_cnt[d], 1);
    }
}

// ---------------- launch 2: one-kernel scan (block scan + atomic base) ------
__global__ void k_scanA() {
    __shared__ int sh[1024];
    __shared__ int base_sh;
    int t = threadIdx.x;
    int i = blockIdx.x * 1024 + t;
    int v = (i < NN) ? g_cnt[i] : 0;
    sh[t] = v;
    __syncthreads();
    for (int o = 1; o < 1024; o <<= 1) {
        int a = (t >= o) ? sh[t - o] : 0;
        __syncthreads();
        sh[t] += a;
        __syncthreads();
    }
    if (t == 1023) base_sh = atomicAdd(&g_total, sh[1023]);
    __syncthreads();
    if (i < NN) {
        g_off[i] = base_sh + sh[t] - v;       // exclusive offset (disjoint ranges)
        g_inv[i] = 1.0f / (float)(v + 1);     // +1 self loop
    }
}

// ------ weight folding helper: stk = [U_top ; W@U_bot], cp = b@U_bot + c ----
__device__ __forceinline__ void fold_one(const float* W, const float* b,
                                         const float* U, const float* c,
                                         int D, float* stk, float* cp, int idx) {
    int k = idx >> 6, o = idx & 63;
    const float* Ub = U + D * 64;
    if (k < D) {
        stk[k * 64 + o] = U[k * 64 + o];
    } else if (k < 2 * D) {
        float s = 0.0f;
        for (int m = 0; m < 64; ++m) s += W[(k - D) * 64 + m] * Ub[m * 64 + o];
        stk[k * 64 + o] = s;
    } else {
        float s = c[o];
        for (int m = 0; m < 64; ++m) s += b[m] * Ub[m * 64 + o];
        cp[o] = s;
    }
}

// ------- launch 3: CSR fill (blocks 0..2047) + weight fold (blocks >=2048) --
#define FILL_BLOCKS 2048
__global__ void k_fill_fold(const int* __restrict__ ei, int E,
                            const float* W1, const float* b1, const float* U1, const float* c1,
                            const float* W2, const float* b2, const float* U2, const float* c2,
                            const float* W3, const float* b3, const float* U3, const float* c3) {
    if (blockIdx.x < FILL_BLOCKS) {
        int is64 = detect64(ei);
        for (int i = blockIdx.x * blockDim.x + threadIdx.x; i < E;
             i += FILL_BLOCKS * blockDim.x) {
            int s, d;
            if (is64) { s = ei[2 * i]; d = ei[2 * (E + i)]; }
            else      { s = ei[i];     d = ei[E + i]; }
            int p = g_off[d] + atomicAdd(&g_fill[d], 1);
            g_csr[p] = s;
        }
    } else {
        const int n1 = (2 * IND + 1) * 64;    // 704
        const int n2 = (2 * HID + 1) * 64;    // 8256
        int idx = (blockIdx.x - FILL_BLOCKS) * 256 + threadIdx.x;
        if (idx < n1)                fold_one(W1, b1, U1, c1, IND, g_stk1, g_cp1, idx);
        else if (idx < n1 + n2)      fold_one(W2, b2, U2, c2, HID, g_stk2, g_cp2, idx - n1);
        else if (idx < n1 + 2 * n2)  fold_one(W3, b3, U3, c3, HID, g_stk3, g_cp3, idx - n1 - n2);
    }
}

// ------- fused layer: gather-mean + GEMM([x||s] @ stk) + bias + relu --------
template <int D>
__global__ void __launch_bounds__(256)
k_layer(const float* __restrict__ x0, float* __restrict__ out3, int layer) {
    constexpr int K    = 2 * D;
    constexpr int TM   = 64;
    constexpr int XSTR = TM + 2;              // 66: conflict-free, 8B rows
    __shared__ __align__(16) float XS[K][XSTR];  // rows 0..D-1 = x, D..2D-1 = mean

    const float* xin = (layer == 1) ? x0 : (layer == 2 ? g_ha : g_hb);
    float*       out = (layer == 1) ? g_ha : (layer == 2 ? g_hb : out3);
    const float* stk = (layer == 1) ? g_stk1 : (layer == 2 ? g_stk2 : g_stk3);
    const float* cp  = (layer == 1) ? g_cp1  : (layer == 2 ? g_cp2  : g_cp3);

    const int t = threadIdx.x;
    const int node0 = blockIdx.x * TM;
    const int warp = t >> 5, lane = t & 31;

    // x tile, transposed (k-major)
    for (int idx = t; idx < TM * D; idx += 256) {
        int n = idx / D, k = idx - n * D;
        int node = node0 + n;
        XS[k][n] = (node < NN) ? xin[node * D + k] : 0.0f;
    }

    if constexpr (D == 64) {
        // gather: 2 nodes per warp (half-warp each), float4 per lane.
        // 4-edge unroll => 8 LDG.128 (~1KB) in flight per warp.
        const int sub = lane >> 4;            // 0/1: which node of this warp
        const int col = (lane & 15) * 4;      // 0..60, float4 column
        for (int r = 0; r < TM / 16; ++r) {
            int n = r * 16 + warp * 2 + sub;
            int node = node0 + n;
            bool valid = node < NN;
            float4 a0, a1, a2, a3;
            if (valid) a0 = *(const float4*)&xin[(size_t)node * 64 + col];  // self
            else       a0 = make_float4(0.f, 0.f, 0.f, 0.f);
            a1 = make_float4(0.f, 0.f, 0.f, 0.f);
            a2 = a1; a3 = a1;
            int e0 = 0, deg = 0;
            if (valid) { e0 = g_off[node]; deg = g_cnt[node]; }
            int last = e0 + deg - 1;
            int dmax = max(deg, __shfl_xor_sync(0xffffffffu, deg, 16));
            if (dmax > 0) {
                auto cidx = [&](int e) { return (deg > 0) ? min(e0 + e, last) : 0; };
                int s0 = g_csr[cidx(0)], s1 = g_csr[cidx(1)];
                int s2 = g_csr[cidx(2)], s3 = g_csr[cidx(3)];
                for (int e = 0; e < dmax; e += 4) {
                    int t0 = g_csr[cidx(e + 4)], t1 = g_csr[cidx(e + 5)];
                    int t2 = g_csr[cidx(e + 6)], t3 = g_csr[cidx(e + 7)];
                    float4 q0 = *(const float4*)&xin[(size_t)s0 * 64 + col];
                    float4 q1 = *(const float4*)&xin[(size_t)s1 * 64 + col];
                    float4 q2 = *(const float4*)&xin[(size_t)s2 * 64 + col];
                    float4 q3 = *(const float4*)&xin[(size_t)s3 * 64 + col];
                    if (e + 0 < deg) { a0.x += q0.x; a0.y += q0.y; a0.z += q0.z; a0.w += q0.w; }
                    if (e + 1 < deg) { a1.x += q1.x; a1.y += q1.y; a1.z += q1.z; a1.w += q1.w; }
                    if (e + 2 < deg) { a2.x += q2.x; a2.y += q2.y; a2.z += q2.z; a2.w += q2.w; }
                    if (e + 3 < deg) { a3.x += q3.x; a3.y += q3.y; a3.z += q3.z; a3.w += q3.w; }
                    s0 = t0; s1 = t1; s2 = t2; s3 = t3;
                }
            }
            if (valid) {
                float iv = g_inv[node];
                XS[D + col + 0][n] = ((a0.x + a1.x) + (a2.x + a3.x)) * iv;
                XS[D + col + 1][n] = ((a0.y + a1.y) + (a2.y + a3.y)) * iv;
                XS[D + col + 2][n] = ((a0.z + a1.z) + (a2.z + a3.z)) * iv;
                XS[D + col + 3][n] = ((a0.w + a1.w) + (a2.w + a3.w)) * iv;
            } else {
                XS[D + col + 0][n] = 0.0f; XS[D + col + 1][n] = 0.0f;
                XS[D + col + 2][n] = 0.0f; XS[D + col + 3][n] = 0.0f;
            }
        }
    } else {
        // small-D gather: warp per node, scalar, 4-edge unroll
        constexpr int NC = (D + 31) / 32;
        for (int r = 0; r < TM / 8; ++r) {
            int n = r * 8 + warp;
            int node = node0 + n;
            if (node >= NN) {
#pragma unroll
                for (int cc = 0; cc < NC; ++cc) {
                    int col = lane + 32 * cc;
                    if (col < D) XS[D + col][n] = 0.0f;
                }
                continue;
            }
            float a0[NC], a1[NC], a2[NC], a3[NC];
#pragma unroll
            for (int cc = 0; cc < NC; ++cc) {
                int col = lane + 32 * cc;
                a0[cc] = (col < D) ? xin[node * D + col] : 0.0f;
                a1[cc] = 0.0f; a2[cc] = 0.0f; a3[cc] = 0.0f;
            }
            const int e0  = g_off[node];
            const int deg = g_cnt[node];
            const int last = e0 + deg - 1;
            if (deg > 0) {
                auto cidx = [&](int e) { return min(e0 + e, last); };
                int s0 = g_csr[cidx(0)], s1 = g_csr[cidx(1)];
                int s2 = g_csr[cidx(2)], s3 = g_csr[cidx(3)];
                for (int e = 0; e < deg; e += 4) {
                    int t0 = g_csr[cidx(e + 4)], t1 = g_csr[cidx(e + 5)];
                    int t2 = g_csr[cidx(e + 6)], t3 = g_csr[cidx(e + 7)];
                    const float* q0 = xin + (size_t)s0 * D;
                    const float* q1 = xin + (size_t)s1 * D;
                    const float* q2 = xin + (size_t)s2 * D;
                    const float* q3 = xin + (size_t)s3 * D;
#pragma unroll
                    for (int cc = 0; cc < NC; ++cc) {
                        int col = lane + 32 * cc;
                        if (col < D) {
                            if (e + 0 < deg) a0[cc] += q0[col];
                            if (e + 1 < deg) a1[cc] += q1[col];
                            if (e + 2 < deg) a2[cc] += q2[col];
                            if (e + 3 < deg) a3[cc] += q3[col];
                        }
                    }
                    s0 = t0; s1 = t1; s2 = t2; s3 = t3;
                }
            }
            float iv = g_inv[node];
#pragma unroll
            for (int cc = 0; cc < NC; ++cc) {
                int col = lane + 32 * cc;
                if (col < D) XS[D + col][n] = ((a0[cc] + a1[cc]) + (a2[cc] + a3[cc])) * iv;
            }
        }
    }
    __syncthreads();

    // GEMM: 256 threads as 16x16, each 4 nodes x 4 outputs, FFMA2 over node pairs
    const int tx = t & 15, ty = t >> 4;
    const int o4 = tx * 4, n4 = ty * 4;
    u64 accA[4], accB[4];
#pragma unroll
    for (int o = 0; o < 4; ++o) { accA[o] = 0ull; accB[o] = 0ull; }

#pragma unroll 4
    for (int k = 0; k < K; ++k) {
        float4 w = __ldg((const float4*)&stk[k * 64 + o4]);
        u64 w0 = pack2(w.x, w.x), w1 = pack2(w.y, w.y);
        u64 w2 = pack2(w.z, w.z), w3 = pack2(w.w, w.w);
        u64 xA = *(const u64*)&XS[k][n4];
        u64 xB = *(const u64*)&XS[k][n4 + 2];
        accA[0] = ffma2(xA, w0, accA[0]);
        accA[1] = ffma2(xA, w1, accA[1]);
        accA[2] = ffma2(xA, w2, accA[2]);
        accA[3] = ffma2(xA, w3, accA[3]);
        accB[0] = ffma2(xB, w0, accB[0]);
        accB[1] = ffma2(xB, w1, accB[1]);
        accB[2] = ffma2(xB, w2, accB[2]);
        accB[3] = ffma2(xB, w3, accB[3]);
    }

    float cb[4];
    cb[0] = __ldg(&cp[o4]);     cb[1] = __ldg(&cp[o4 + 1]);
    cb[2] = __ldg(&cp[o4 + 2]); cb[3] = __ldg(&cp[o4 + 3]);

    float r0[4], r1[4], r2[4], r3[4];
#pragma unroll
    for (int o = 0; o < 4; ++o) {
        float lo, hi;
        unpack2(accA[o], lo, hi);
        r0[o] = fmaxf(lo + cb[o], 0.0f);
        r1[o] = fmaxf(hi + cb[o], 0.0f);
        unpack2(accB[o], lo, hi);
        r2[o] = fmaxf(lo + cb[o], 0.0f);
        r3[o] = fmaxf(hi + cb[o], 0.0f);
    }
    // layer-3 out base (d_out+200002 floats) is only 8B-aligned: float2 stores.
#pragma unroll
    for (int i = 0; i < 4; ++i) {
        int node = node0 + n4 + i;
        if (node < NN) {
            const float* rr = (i == 0) ? r0 : (i == 1) ? r1 : (i == 2) ? r2 : r3;
            float2* p = (float2*)&out[node * 64 + o4];
            p[0] = make_float2(rr[0], rr[1]);
            p[1] = make_float2(rr[2], rr[3]);
        }
    }
}

// ------- launch 7: heads (state[N,2], sigmoid-mean, mean) + fused final -----
__global__ void __launch_bounds__(256)
k_heads(const float* __restrict__ h, const float* __restrict__ Ws,
        const float* __restrict__ bs, const float* __restrict__ Wst,
        const float* __restrict__ bst, const float* __restrict__ Wo,
        const float* __restrict__ bo, float* __restrict__ out_state,
        float* __restrict__ out_scalars) {
    __shared__ float wst[8], woc[8];
    int t = threadIdx.x, warp = t >> 5, lane = t & 31;
    int gw = blockIdx.x * 8 + warp;

    float ws0a = Ws[lane * 2 + 0], ws0b = Ws[(lane + 32) * 2 + 0];
    float ws1a = Ws[lane * 2 + 1], ws1b = Ws[(lane + 32) * 2 + 1];
    float wsta = Wst[lane], wstb = Wst[lane + 32];
    float woa  = Wo[lane],  wob  = Wo[lane + 32];
    float bs0 = bs[0], bs1 = bs[1], bstv = bst[0], bov = bo[0];

    float sum_st = 0.0f, sum_oc = 0.0f;
    for (int node = gw; node < NN; node += 8192) {
        float h0 = h[node * 64 + lane];
        float h1 = h[node * 64 + lane + 32];
        float d0 = h0 * ws0a + h1 * ws0b;
        float d1 = h0 * ws1a + h1 * ws1b;
        float d2 = h0 * wsta + h1 * wstb;
        float d3 = h0 * woa  + h1 * wob;
#pragma unroll
        for (int o = 16; o > 0; o >>= 1) {
            d0 += __shfl_xor_sync(0xffffffffu, d0, o);
            d1 += __shfl_xor_sync(0xffffffffu, d1, o);
            d2 += __shfl_xor_sync(0xffffffffu, d2, o);
            d3 += __shfl_xor_sync(0xffffffffu, d3, o);
        }
        if (lane == 0) {
            out_state[node * 2 + 0] = d0 + bs0;
            out_state[node * 2 + 1] = d1 + bs1;
            sum_st += 1.0f / (1.0f + expf(-(d2 + bstv)));
            sum_oc += d3 + bov;
        }
    }
    if (lane == 0) { wst[warp] = sum_st; woc[warp] = sum_oc; }
    __syncthreads();
    if (t == 0) {
        float a = 0.0f, b = 0.0f;
        for (int i = 0; i < 8; ++i) { a += wst[i]; b += woc[i]; }
        g_pst[blockIdx.x] = a;
        g_poc[blockIdx.x] = b;
    }
    // fused final reduce: last block to finish sums all partials
    __threadfence();
    __shared__ unsigned isLast;
    if (t == 0) isLast = (atomicAdd(&g_done, 1u) == gridDim.x - 1u) ? 1u : 0u;
    __syncthreads();
    if (isLast) {
        __shared__ float ra[256], rb[256];
        volatile float* vp = g_pst;
        volatile float* vq = g_poc;
        float a = 0.0f, b = 0.0f;
        for (int i = t; i < 1024; i += 256) { a += vp[i]; b += vq[i]; }
        ra[t] = a; rb[t] = b;
        __syncthreads();
        for (int o = 128; o > 0; o >>= 1) {
            if (t < o) { ra[t] += ra[t + o]; rb[t] += rb[t + o]; }
            __syncthreads();
        }
        if (t == 0) {
            out_scalars[0] = ra[0] / (float)NN;
            out_scalars[1] = rb[0] / (float)NN;
            g_done = 0u;                      // reset for next replay
        }
    }
}

// ---------------- launch -----------------------------------------------------
extern "C" void kernel_launch(void* const* d_in, const int* in_sizes, int n_in,
                              void* d_out, int out_size) {
    const float* x   = (const float*)d_in[0];
    const int*   ei  = (const int*)d_in[1];
    const float* W1 = (const float*)d_in[2],  *b1 = (const float*)d_in[3];
    const float* U1 = (const float*)d_in[4],  *c1 = (const float*)d_in[5];
    const float* W2 = (const float*)d_in[6],  *b2 = (const float*)d_in[7];
    const float* U2 = (const float*)d_in[8],  *c2 = (const float*)d_in[9];
    const float* W3 = (const float*)d_in[10], *b3 = (const float*)d_in[11];
    const float* U3 = (const float*)d_in[12], *c3 = (const float*)d_in[13];
    const float* Ws = (const float*)d_in[14], *bs = (const float*)d_in[15];
    const float* Wst = (const float*)d_in[16], *bst = (const float*)d_in[17];
    const float* Wo = (const float*)d_in[18],  *bo = (const float*)d_in[19];
    float* out = (float*)d_out;

    int E = in_sizes[1] / 2;

    int fold_elems  = (2 * IND + 1) * 64 + 2 * (2 * HID + 1) * 64;
    int fold_blocks = (fold_elems + 255) / 256;

    k_zero <<<(NN + 255) / 256, 256>>>();                              // 0
    k_hist <<<2048, 256>>>(ei, E);                                     // 1
    k_scanA<<<(NN + 1023) / 1024, 1024>>>();                           // 2
    k_fill_fold<<<FILL_BLOCKS + fold_blocks, 256>>>(ei, E,             // 3
                                                    W1, b1, U1, c1,
                                                    W2, b2, U2, c2,
                                                    W3, b3, U3, c3);
    int grid = (NN + 63) / 64;
    k_layer<IND><<<grid, 256>>>(x, nullptr, 1);                        // 4
    k_layer<HID><<<grid, 256>>>(nullptr, nullptr, 2);                  // 5 <- ncu
    k_layer<HID><<<grid, 256>>>(nullptr, out + 200002, 3);             // 6
    k_heads<<<1024, 256>>>(out + 200002, Ws, bs, Wst, bst, Wo, bo,     // 7
                           out, out + 200000);
}